// round 10
// baseline (speedup 1.0000x reference)
#include <cuda_runtime.h>
#include <math.h>
#include <stdint.h>

#define SEQ   16384
#define HID   1152
#define HEADS 16
#define HD    72
#define INTER 4304
#define NWIN  256

// ---------------------------------------------------------------------------
// Scratch (device globals; no runtime allocation allowed)
// ---------------------------------------------------------------------------
__device__ float g_h   [(size_t)SEQ * HID];
__device__ float g_qkv [(size_t)SEQ * 3 * HID];
__device__ float g_attn[(size_t)SEQ * HID];
__device__ float g_x1  [(size_t)SEQ * HID];
__device__ float g_m   [(size_t)SEQ * INTER];
__device__ float g_wqkv[(size_t)HID * 3 * HID];
__device__ float g_wproj[(size_t)HID * HID];
__device__ float g_wfc1[(size_t)HID * INTER];
__device__ float g_wfc2[(size_t)INTER * HID];

__device__ __forceinline__ float tf32r(float f)
{
    uint32_t u;
    asm("cvt.rna.tf32.f32 %0, %1;" : "=r"(u) : "f"(f));
    return __uint_as_float(u);
}

// ---------------------------------------------------------------------------
// Round a weight matrix to tf32
// ---------------------------------------------------------------------------
__global__ void round_w_kernel(const float* __restrict__ in,
                               float* __restrict__ out, int n4)
{
    int i = blockIdx.x * blockDim.x + threadIdx.x;
    if (i >= n4) return;
    float4 v = ((const float4*)in)[i];
    v.x = tf32r(v.x); v.y = tf32r(v.y); v.z = tf32r(v.z); v.w = tf32r(v.w);
    ((float4*)out)[i] = v;
}

// ---------------------------------------------------------------------------
// LayerNorm: one warp per row, output rounded to tf32
// ---------------------------------------------------------------------------
__global__ void ln_kernel(const float* __restrict__ in,
                          const float* __restrict__ w,
                          const float* __restrict__ b,
                          float* __restrict__ out)
{
    int warp = (blockIdx.x * blockDim.x + threadIdx.x) >> 5;
    int lane = threadIdx.x & 31;
    if (warp >= SEQ) return;

    const float* row = in + (size_t)warp * HID;
    float v[36];
    float s = 0.f, s2 = 0.f;
#pragma unroll
    for (int i = 0; i < 36; i++) {
        v[i] = row[lane + 32 * i];
        s  += v[i];
        s2 += v[i] * v[i];
    }
#pragma unroll
    for (int o = 16; o > 0; o >>= 1) {
        s  += __shfl_xor_sync(0xFFFFFFFFu, s,  o);
        s2 += __shfl_xor_sync(0xFFFFFFFFu, s2, o);
    }
    float mean = s * (1.0f / HID);
    float var  = s2 * (1.0f / HID) - mean * mean;
    float rstd = rsqrtf(var + 1e-6f);

    float* orow = out + (size_t)warp * HID;
#pragma unroll
    for (int i = 0; i < 36; i++) {
        int c = lane + 32 * i;
        orow[c] = tf32r((v[i] - mean) * rstd * w[c] + b[c]);
    }
}

// ---------------------------------------------------------------------------
// tf32 tensor-core GEMM (inputs pre-rounded; no inner-loop cvt)
// 256x128x32 CTA tile, 256 threads, 8 warps (4x2), 64x64 per warp,
// 3-stage cp.async pipeline.
// EPI: 0 = bias, 1 = bias + residual, 2 = bias + gelu (tf32-rounded out)
// ---------------------------------------------------------------------------
#define BM 256
#define BN 128
#define BK 32
#define NSTAGE 3
#define ASTRIDE 36
#define BSTRIDE 136
#define A_TILE (BM * ASTRIDE)    // 9216 floats
#define B_TILE (BK * BSTRIDE)    // 4352 floats
#define GEMM_SMEM (NSTAGE * (A_TILE + B_TILE) * 4)   // 162816 bytes

#define MMA_TF32(acc, a0, a1, a2, a3, b0, b1)                                  \
    asm volatile(                                                              \
        "mma.sync.aligned.m16n8k8.row.col.f32.tf32.tf32.f32 "                  \
        "{%0,%1,%2,%3}, {%4,%5,%6,%7}, {%8,%9}, {%0,%1,%2,%3};\n"              \
        : "+f"(acc[0]), "+f"(acc[1]), "+f"(acc[2]), "+f"(acc[3])               \
        : "r"(a0), "r"(a1), "r"(a2), "r"(a3), "r"(b0), "r"(b1))

template <int EPI>
__global__ __launch_bounds__(256) void gemm_tf32(
    const float* __restrict__ A, const float* __restrict__ B,
    const float* __restrict__ bias, const float* __restrict__ resid,
    float* __restrict__ C, int M, int N, int K)
{
    extern __shared__ float smf[];
    float* sA = smf;                       // [NSTAGE][256][36]
    float* sB = smf + NSTAGE * A_TILE;     // [NSTAGE][32][136]

    const int tid  = threadIdx.x;
    const int lane = tid & 31, warp = tid >> 5;
    const int g = lane >> 2, t = lane & 3;
    const int wm = (warp >> 1) * 64, wn = (warp & 1) * 64;
    const int rowBase = blockIdx.y * BM, colBase = blockIdx.x * BN;

    float acc[4][8][4];
#pragma unroll
    for (int i = 0; i < 4; i++)
#pragma unroll
        for (int j = 0; j < 8; j++)
#pragma unroll
            for (int c = 0; c < 4; c++) acc[i][j][c] = 0.f;

    const int nkt = (K + BK - 1) / BK;

    auto loadA = [&](int stage, int k0) {
#pragma unroll
        for (int i = 0; i < 8; i++) {
            int c  = tid + i * 256;
            int m  = c >> 3;
            int kc = (c & 7) * 4;
            int gk = k0 + kc;
            int sz = (gk < K) ? 16 : 0;
            const float* src = A + (size_t)(rowBase + m) * K + min(gk, K - 4);
            uint32_t dst = (uint32_t)__cvta_generic_to_shared(
                sA + stage * A_TILE + m * ASTRIDE + kc);
            asm volatile("cp.async.cg.shared.global [%0], [%1], 16, %2;\n"
                         :: "r"(dst), "l"(src), "r"(sz));
        }
    };
    auto loadB = [&](int stage, int k0) {
#pragma unroll
        for (int i = 0; i < 4; i++) {
            int c  = tid + i * 256;
            int kr = c >> 5;
            int nc = (c & 31) * 4;
            int gk = k0 + kr;
            int gn = colBase + nc;
            int sz = (gk < K && gn < N) ? 16 : 0;
            const float* src = B + (size_t)min(gk, K - 1) * N + min(gn, N - 4);
            uint32_t dst = (uint32_t)__cvta_generic_to_shared(
                sB + stage * B_TILE + kr * BSTRIDE + nc);
            asm volatile("cp.async.cg.shared.global [%0], [%1], 16, %2;\n"
                         :: "r"(dst), "l"(src), "r"(sz));
        }
    };

    // Prologue: stages 0 and 1
    loadA(0, 0); loadB(0, 0);
    asm volatile("cp.async.commit_group;\n");
    if (nkt > 1) { loadA(1, BK); loadB(1, BK); }
    asm volatile("cp.async.commit_group;\n");

    for (int kt = 0; kt < nkt; kt++) {
        if (kt + 1 < nkt)
            asm volatile("cp.async.wait_group 1;\n");
        else
            asm volatile("cp.async.wait_group 0;\n");
        __syncthreads();

        // Prefetch stage kt+2 (its buffer was consumed at kt-1; barrier passed)
        if (kt + 2 < nkt) {
            int ps = (kt + 2) % NSTAGE;
            loadA(ps, (kt + 2) * BK);
            loadB(ps, (kt + 2) * BK);
        }
        asm volatile("cp.async.commit_group;\n");

        const float* a_s = sA + (kt % NSTAGE) * A_TILE;
        const float* b_s = sB + (kt % NSTAGE) * B_TILE;

#pragma unroll
        for (int ks = 0; ks < 4; ks++) {
            const int k8 = ks * 8;
            uint32_t af[4][4], bf[8][2];
#pragma unroll
            for (int mt = 0; mt < 4; mt++) {
                int r = wm + mt * 16 + g;
                af[mt][0] = __float_as_uint(a_s[(r    ) * ASTRIDE + k8 + t    ]);
                af[mt][1] = __float_as_uint(a_s[(r + 8) * ASTRIDE + k8 + t    ]);
                af[mt][2] = __float_as_uint(a_s[(r    ) * ASTRIDE + k8 + t + 4]);
                af[mt][3] = __float_as_uint(a_s[(r + 8) * ASTRIDE + k8 + t + 4]);
            }
#pragma unroll
            for (int nt = 0; nt < 8; nt++) {
                int cc = wn + nt * 8 + g;
                bf[nt][0] = __float_as_uint(b_s[(k8 + t    ) * BSTRIDE + cc]);
                bf[nt][1] = __float_as_uint(b_s[(k8 + t + 4) * BSTRIDE + cc]);
            }
#pragma unroll
            for (int mt = 0; mt < 4; mt++)
#pragma unroll
                for (int nt = 0; nt < 8; nt++)
                    MMA_TF32(acc[mt][nt], af[mt][0], af[mt][1], af[mt][2],
                             af[mt][3], bf[nt][0], bf[nt][1]);
        }
        __syncthreads();
    }

#pragma unroll
    for (int mt = 0; mt < 4; mt++) {
#pragma unroll
        for (int nt = 0; nt < 8; nt++) {
            int col = colBase + wn + nt * 8 + 2 * t;
            if (col < N) {
                float b0 = bias[col], b1 = bias[col + 1];
#pragma unroll
                for (int half = 0; half < 2; half++) {
                    int row = rowBase + wm + mt * 16 + g + half * 8;
                    float v0 = acc[mt][nt][half * 2 + 0] + b0;
                    float v1 = acc[mt][nt][half * 2 + 1] + b1;
                    if (EPI == 1) {
                        v0 += resid[(size_t)row * N + col];
                        v1 += resid[(size_t)row * N + col + 1];
                    }
                    if (EPI == 2) {
                        float u0 = v0, u1 = v1;
                        float t0 = 0.7978845608028654f * (u0 + 0.044715f * u0 * u0 * u0);
                        float t1 = 0.7978845608028654f * (u1 + 0.044715f * u1 * u1 * u1);
                        v0 = tf32r(0.5f * u0 * (1.f + tanhf(t0)));
                        v1 = tf32r(0.5f * u1 * (1.f + tanhf(t1)));
                    }
                    *(float2*)&C[(size_t)row * N + col] = make_float2(v0, v1);
                }
            }
        }
    }
}

// ---------------------------------------------------------------------------
// Windowed attention with tf32 MMA; RoPE fused into the loader.
// ---------------------------------------------------------------------------
#define QST 76
#define SST 68
#define ATTN_SMEM ((3 * 64 * QST + 64 * SST) * 4)

__global__ __launch_bounds__(128) void attn_kernel(const float* __restrict__ qkv,
                                                   const float* __restrict__ cosb,
                                                   const float* __restrict__ sinb,
                                                   float* __restrict__ out)
{
    extern __shared__ float sm[];
    float* sq = sm;
    float* sk = sq + 64 * QST;
    float* sv = sk + 64 * QST;
    float* ss = sv + 64 * QST;

    const int w   = blockIdx.x >> 4;
    const int h   = blockIdx.x & 15;
    const int tid = threadIdx.x;
    const float scale = 0.11785113019775793f;   // 72^-0.5

    for (int p = tid; p < 64 * 36; p += 128) {
        int r = p / 36, d = p % 36;
        int tok = w * 64 + r;
        size_t base = (size_t)tok * (3 * HID) + h * HD;
        float c = cosb[tok * HD + d];
        float s = sinb[tok * HD + d];

        float q0 = qkv[base + d], q1 = qkv[base + d + 36];
        sq[r * QST + d]      = tf32r((q0 * c - q1 * s) * scale);
        sq[r * QST + d + 36] = tf32r((q1 * c + q0 * s) * scale);

        float k0 = qkv[base + HID + d], k1 = qkv[base + HID + d + 36];
        sk[r * QST + d]      = tf32r(k0 * c - k1 * s);
        sk[r * QST + d + 36] = tf32r(k1 * c + k0 * s);

        sv[r * QST + d]      = tf32r(qkv[base + 2 * HID + d]);
        sv[r * QST + d + 36] = tf32r(qkv[base + 2 * HID + d + 36]);
    }
    __syncthreads();

    const int lane = tid & 31, warp = tid >> 5;
    const int g = lane >> 2, t = lane & 3;
    const int rw = warp * 16;

    // scores = Q @ K^T
    {
        float c1[8][4];
#pragma unroll
        for (int nt = 0; nt < 8; nt++)
#pragma unroll
            for (int c = 0; c < 4; c++) c1[nt][c] = 0.f;

#pragma unroll
        for (int ks = 0; ks < 9; ks++) {
            int k8 = ks * 8;
            uint32_t a0 = __float_as_uint(sq[(rw + g    ) * QST + k8 + t    ]);
            uint32_t a1 = __float_as_uint(sq[(rw + g + 8) * QST + k8 + t    ]);
            uint32_t a2 = __float_as_uint(sq[(rw + g    ) * QST + k8 + t + 4]);
            uint32_t a3 = __float_as_uint(sq[(rw + g + 8) * QST + k8 + t + 4]);
#pragma unroll
            for (int nt = 0; nt < 8; nt++) {
                uint32_t b0 = __float_as_uint(sk[(nt * 8 + g) * QST + k8 + t    ]);
                uint32_t b1 = __float_as_uint(sk[(nt * 8 + g) * QST + k8 + t + 4]);
                MMA_TF32(c1[nt], a0, a1, a2, a3, b0, b1);
            }
        }
#pragma unroll
        for (int nt = 0; nt < 8; nt++) {
            *(float2*)&ss[(rw + g    ) * SST + nt * 8 + 2 * t] =
                make_float2(c1[nt][0], c1[nt][1]);
            *(float2*)&ss[(rw + g + 8) * SST + nt * 8 + 2 * t] =
                make_float2(c1[nt][2], c1[nt][3]);
        }
    }
    __syncthreads();

    // softmax
    {
        int r = tid >> 1, hf = tid & 1;
        float* row = ss + r * SST + hf * 32;
        float mx = -1e30f;
#pragma unroll
        for (int j = 0; j < 32; j++) mx = fmaxf(mx, row[j]);
        mx = fmaxf(mx, __shfl_xor_sync(0xFFFFFFFFu, mx, 1));
        float e[32], sum = 0.f;
#pragma unroll
        for (int j = 0; j < 32; j++) { e[j] = __expf(row[j] - mx); sum += e[j]; }
        sum += __shfl_xor_sync(0xFFFFFFFFu, sum, 1);
        float inv = 1.f / sum;
#pragma unroll
        for (int j = 0; j < 32; j++) row[j] = tf32r(e[j] * inv);
    }
    __syncthreads();

    // out = P @ V
    {
        float c2[9][4];
#pragma unroll
        for (int nt = 0; nt < 9; nt++)
#pragma unroll
            for (int c = 0; c < 4; c++) c2[nt][c] = 0.f;

#pragma unroll
        for (int ks = 0; ks < 8; ks++) {
            int k8 = ks * 8;
            uint32_t a0 = __float_as_uint(ss[(rw + g    ) * SST + k8 + t    ]);
            uint32_t a1 = __float_as_uint(ss[(rw + g + 8) * SST + k8 + t    ]);
            uint32_t a2 = __float_as_uint(ss[(rw + g    ) * SST + k8 + t + 4]);
            uint32_t a3 = __float_as_uint(ss[(rw + g + 8) * SST + k8 + t + 4]);
#pragma unroll
            for (int nt = 0; nt < 9; nt++) {
                uint32_t b0 = __float_as_uint(sv[(k8 + t    ) * QST + nt * 8 + g]);
                uint32_t b1 = __float_as_uint(sv[(k8 + t + 4) * QST + nt * 8 + g]);
                MMA_TF32(c2[nt], a0, a1, a2, a3, b0, b1);
            }
        }

#pragma unroll
        for (int nt = 0; nt < 9; nt++) {
            size_t o0 = (size_t)(w * 64 + rw + g) * HID + h * HD + nt * 8 + 2 * t;
            size_t o1 = o0 + (size_t)8 * HID;
            *(float2*)&out[o0] = make_float2(tf32r(c2[nt][0]), tf32r(c2[nt][1]));
            *(float2*)&out[o1] = make_float2(tf32r(c2[nt][2]), tf32r(c2[nt][3]));
        }
    }
}

// ---------------------------------------------------------------------------
// Launch
// ---------------------------------------------------------------------------
extern "C" void kernel_launch(void* const* d_in, const int* in_sizes, int n_in,
                              void* d_out, int out_size)
{
    const float* x      = (const float*)d_in[0];
    const float* cosb   = (const float*)d_in[1];
    const float* sinb   = (const float*)d_in[2];
    const float* qkv_w  = (const float*)d_in[4];
    const float* qkv_b  = (const float*)d_in[5];
    const float* proj_w = (const float*)d_in[6];
    const float* proj_b = (const float*)d_in[7];
    const float* ln1_w  = (const float*)d_in[8];
    const float* ln1_b  = (const float*)d_in[9];
    const float* ln2_w  = (const float*)d_in[10];
    const float* ln2_b  = (const float*)d_in[11];
    const float* fc1_w  = (const float*)d_in[12];
    const float* fc1_b  = (const float*)d_in[13];
    const float* fc2_w  = (const float*)d_in[14];
    const float* fc2_b  = (const float*)d_in[15];
    float* out = (float*)d_out;

    float *ph, *pqkv, *pattn, *px1, *pm, *pwqkv, *pwproj, *pwfc1, *pwfc2;
    cudaGetSymbolAddress((void**)&ph,     g_h);
    cudaGetSymbolAddress((void**)&pqkv,   g_qkv);
    cudaGetSymbolAddress((void**)&pattn,  g_attn);
    cudaGetSymbolAddress((void**)&px1,    g_x1);
    cudaGetSymbolAddress((void**)&pm,     g_m);
    cudaGetSymbolAddress((void**)&pwqkv,  g_wqkv);
    cudaGetSymbolAddress((void**)&pwproj, g_wproj);
    cudaGetSymbolAddress((void**)&pwfc1,  g_wfc1);
    cudaGetSymbolAddress((void**)&pwfc2,  g_wfc2);

    cudaFuncSetAttribute(attn_kernel,
                         cudaFuncAttributeMaxDynamicSharedMemorySize, ATTN_SMEM);
    cudaFuncSetAttribute(gemm_tf32<0>,
                         cudaFuncAttributeMaxDynamicSharedMemorySize, GEMM_SMEM);
    cudaFuncSetAttribute(gemm_tf32<1>,
                         cudaFuncAttributeMaxDynamicSharedMemorySize, GEMM_SMEM);
    cudaFuncSetAttribute(gemm_tf32<2>,
                         cudaFuncAttributeMaxDynamicSharedMemorySize, GEMM_SMEM);

    // 0) round weights to tf32
    {
        int n;
        n = HID * 3 * HID / 4;
        round_w_kernel<<<(n + 255) / 256, 256>>>(qkv_w,  pwqkv,  n);
        n = HID * HID / 4;
        round_w_kernel<<<(n + 255) / 256, 256>>>(proj_w, pwproj, n);
        n = HID * INTER / 4;
        round_w_kernel<<<(n + 255) / 256, 256>>>(fc1_w,  pwfc1,  n);
        n = INTER * HID / 4;
        round_w_kernel<<<(n + 255) / 256, 256>>>(fc2_w,  pwfc2,  n);
    }

    // 1) LN1(x) -> h
    ln_kernel<<<SEQ / 8, 256>>>(x, ln1_w, ln1_b, ph);

    // 2) qkv = h @ qkv_w + qkv_b
    gemm_tf32<0><<<dim3(3 * HID / 128, SEQ / 256), 256, GEMM_SMEM>>>(
        ph, pwqkv, qkv_b, nullptr, pqkv, SEQ, 3 * HID, HID);

    // 3) windowed attention (RoPE fused)
    attn_kernel<<<NWIN * HEADS, 128, ATTN_SMEM>>>(pqkv, cosb, sinb, pattn);

    // 4) x1 = x + attn @ proj_w + proj_b
    gemm_tf32<1><<<dim3(HID / 128, SEQ / 256), 256, GEMM_SMEM>>>(
        pattn, pwproj, proj_b, x, px1, SEQ, HID, HID);

    // 5) LN2(x1) -> h
    ln_kernel<<<SEQ / 8, 256>>>(px1, ln2_w, ln2_b, ph);

    // 6) m = gelu(h @ fc1_w + fc1_b)
    gemm_tf32<2><<<dim3((INTER + 127) / 128, SEQ / 256), 256, GEMM_SMEM>>>(
        ph, pwfc1, fc1_b, nullptr, pm, SEQ, INTER, HID);

    // 7) out = x1 + m @ fc2_w + fc2_b
    gemm_tf32<1><<<dim3(HID / 128, SEQ / 256), 256, GEMM_SMEM>>>(
        pm, pwfc2, fc2_b, px1, out, SEQ, HID, INTER);
}

// round 14
// speedup vs baseline: 1.1929x; 1.1929x over previous
#include <cuda_runtime.h>
#include <math.h>
#include <stdint.h>

#define SEQ   16384
#define HID   1152
#define HEADS 16
#define HD    72
#define INTER 4304
#define NWIN  256

// ---------------------------------------------------------------------------
// Scratch (device globals; no runtime allocation allowed)
// ---------------------------------------------------------------------------
__device__ float g_h   [(size_t)SEQ * HID];
__device__ float g_qkv [(size_t)SEQ * 3 * HID];
__device__ float g_attn[(size_t)SEQ * HID];
__device__ float g_x1  [(size_t)SEQ * HID];
__device__ float g_m   [(size_t)SEQ * INTER];
__device__ float g_wqkv[(size_t)HID * 3 * HID];
__device__ float g_wproj[(size_t)HID * HID];
__device__ float g_wfc1[(size_t)HID * INTER];
__device__ float g_wfc2[(size_t)INTER * HID];

__device__ __forceinline__ float tf32r(float f)
{
    uint32_t u;
    asm("cvt.rna.tf32.f32 %0, %1;" : "=r"(u) : "f"(f));
    return __uint_as_float(u);
}

// ---------------------------------------------------------------------------
// Round a weight matrix to tf32
// ---------------------------------------------------------------------------
__global__ void round_w_kernel(const float* __restrict__ in,
                               float* __restrict__ out, int n4)
{
    int i = blockIdx.x * blockDim.x + threadIdx.x;
    if (i >= n4) return;
    float4 v = ((const float4*)in)[i];
    v.x = tf32r(v.x); v.y = tf32r(v.y); v.z = tf32r(v.z); v.w = tf32r(v.w);
    ((float4*)out)[i] = v;
}

// ---------------------------------------------------------------------------
// LayerNorm: one warp per row, output rounded to tf32
// ---------------------------------------------------------------------------
__global__ void ln_kernel(const float* __restrict__ in,
                          const float* __restrict__ w,
                          const float* __restrict__ b,
                          float* __restrict__ out)
{
    int warp = (blockIdx.x * blockDim.x + threadIdx.x) >> 5;
    int lane = threadIdx.x & 31;
    if (warp >= SEQ) return;

    const float* row = in + (size_t)warp * HID;
    float v[36];
    float s = 0.f, s2 = 0.f;
#pragma unroll
    for (int i = 0; i < 36; i++) {
        v[i] = row[lane + 32 * i];
        s  += v[i];
        s2 += v[i] * v[i];
    }
#pragma unroll
    for (int o = 16; o > 0; o >>= 1) {
        s  += __shfl_xor_sync(0xFFFFFFFFu, s,  o);
        s2 += __shfl_xor_sync(0xFFFFFFFFu, s2, o);
    }
    float mean = s * (1.0f / HID);
    float var  = s2 * (1.0f / HID) - mean * mean;
    float rstd = rsqrtf(var + 1e-6f);

    float* orow = out + (size_t)warp * HID;
#pragma unroll
    for (int i = 0; i < 36; i++) {
        int c = lane + 32 * i;
        orow[c] = tf32r((v[i] - mean) * rstd * w[c] + b[c]);
    }
}

// ---------------------------------------------------------------------------
// tf32 tensor-core GEMM (inputs pre-rounded; no inner-loop cvt)
// 128x128x32 CTA tile, 128 threads = 4 warps (2x2), 64x64 per warp,
// 3-stage cp.async pipeline -> 2 CTAs/SM.
// EPI: 0 = bias, 1 = bias + residual, 2 = bias + gelu (tf32-rounded out)
// ---------------------------------------------------------------------------
#define BM 128
#define BN 128
#define BK 32
#define NSTAGE 3
#define ASTRIDE 36
#define BSTRIDE 136
#define A_TILE (BM * ASTRIDE)    // 4608 floats
#define B_TILE (BK * BSTRIDE)    // 4352 floats
#define GEMM_SMEM (NSTAGE * (A_TILE + B_TILE) * 4)   // 107520 bytes

#define MMA_TF32(acc, a0, a1, a2, a3, b0, b1)                                  \
    asm volatile(                                                              \
        "mma.sync.aligned.m16n8k8.row.col.f32.tf32.tf32.f32 "                  \
        "{%0,%1,%2,%3}, {%4,%5,%6,%7}, {%8,%9}, {%0,%1,%2,%3};\n"              \
        : "+f"(acc[0]), "+f"(acc[1]), "+f"(acc[2]), "+f"(acc[3])               \
        : "r"(a0), "r"(a1), "r"(a2), "r"(a3), "r"(b0), "r"(b1))

template <int EPI>
__global__ __launch_bounds__(128) void gemm_tf32(
    const float* __restrict__ A, const float* __restrict__ B,
    const float* __restrict__ bias, const float* __restrict__ resid,
    float* __restrict__ C, int M, int N, int K)
{
    extern __shared__ float smf[];
    float* sA = smf;                       // [NSTAGE][128][36]
    float* sB = smf + NSTAGE * A_TILE;     // [NSTAGE][32][136]

    const int tid  = threadIdx.x;
    const int lane = tid & 31, warp = tid >> 5;
    const int g = lane >> 2, t = lane & 3;
    const int wm = (warp >> 1) * 64, wn = (warp & 1) * 64;
    const int rowBase = blockIdx.y * BM, colBase = blockIdx.x * BN;

    float acc[4][8][4];
#pragma unroll
    for (int i = 0; i < 4; i++)
#pragma unroll
        for (int j = 0; j < 8; j++)
#pragma unroll
            for (int c = 0; c < 4; c++) acc[i][j][c] = 0.f;

    const int nkt = (K + BK - 1) / BK;

    auto loadA = [&](int stage, int k0) {
#pragma unroll
        for (int i = 0; i < 8; i++) {
            int c  = tid + i * 128;
            int m  = c >> 3;
            int kc = (c & 7) * 4;
            int gk = k0 + kc;
            int sz = (gk < K) ? 16 : 0;
            const float* src = A + (size_t)(rowBase + m) * K + min(gk, K - 4);
            uint32_t dst = (uint32_t)__cvta_generic_to_shared(
                sA + stage * A_TILE + m * ASTRIDE + kc);
            asm volatile("cp.async.cg.shared.global [%0], [%1], 16, %2;\n"
                         :: "r"(dst), "l"(src), "r"(sz));
        }
    };
    auto loadB = [&](int stage, int k0) {
#pragma unroll
        for (int i = 0; i < 8; i++) {
            int c  = tid + i * 128;
            int kr = c >> 5;
            int nc = (c & 31) * 4;
            int gk = k0 + kr;
            int gn = colBase + nc;
            int sz = (gk < K && gn < N) ? 16 : 0;
            const float* src = B + (size_t)min(gk, K - 1) * N + min(gn, N - 4);
            uint32_t dst = (uint32_t)__cvta_generic_to_shared(
                sB + stage * B_TILE + kr * BSTRIDE + nc);
            asm volatile("cp.async.cg.shared.global [%0], [%1], 16, %2;\n"
                         :: "r"(dst), "l"(src), "r"(sz));
        }
    };

    // Prologue: stages 0 and 1
    loadA(0, 0); loadB(0, 0);
    asm volatile("cp.async.commit_group;\n");
    if (nkt > 1) { loadA(1, BK); loadB(1, BK); }
    asm volatile("cp.async.commit_group;\n");

    for (int kt = 0; kt < nkt; kt++) {
        if (kt + 1 < nkt)
            asm volatile("cp.async.wait_group 1;\n");
        else
            asm volatile("cp.async.wait_group 0;\n");
        __syncthreads();

        // Prefetch stage kt+2 (buffer (kt-1)%3 was consumed before last barrier)
        if (kt + 2 < nkt) {
            int ps = (kt + 2) % NSTAGE;
            loadA(ps, (kt + 2) * BK);
            loadB(ps, (kt + 2) * BK);
        }
        asm volatile("cp.async.commit_group;\n");

        const float* a_s = sA + (kt % NSTAGE) * A_TILE;
        const float* b_s = sB + (kt % NSTAGE) * B_TILE;

#pragma unroll
        for (int ks = 0; ks < 4; ks++) {
            const int k8 = ks * 8;
            uint32_t af[4][4], bf[8][2];
#pragma unroll
            for (int mt = 0; mt < 4; mt++) {
                int r = wm + mt * 16 + g;
                af[mt][0] = __float_as_uint(a_s[(r    ) * ASTRIDE + k8 + t    ]);
                af[mt][1] = __float_as_uint(a_s[(r + 8) * ASTRIDE + k8 + t    ]);
                af[mt][2] = __float_as_uint(a_s[(r    ) * ASTRIDE + k8 + t + 4]);
                af[mt][3] = __float_as_uint(a_s[(r + 8) * ASTRIDE + k8 + t + 4]);
            }
#pragma unroll
            for (int nt = 0; nt < 8; nt++) {
                int cc = wn + nt * 8 + g;
                bf[nt][0] = __float_as_uint(b_s[(k8 + t    ) * BSTRIDE + cc]);
                bf[nt][1] = __float_as_uint(b_s[(k8 + t + 4) * BSTRIDE + cc]);
            }
#pragma unroll
            for (int mt = 0; mt < 4; mt++)
#pragma unroll
                for (int nt = 0; nt < 8; nt++)
                    MMA_TF32(acc[mt][nt], af[mt][0], af[mt][1], af[mt][2],
                             af[mt][3], bf[nt][0], bf[nt][1]);
        }
        __syncthreads();
    }

#pragma unroll
    for (int mt = 0; mt < 4; mt++) {
#pragma unroll
        for (int nt = 0; nt < 8; nt++) {
            int col = colBase + wn + nt * 8 + 2 * t;
            if (col < N) {
                float b0 = bias[col], b1 = bias[col + 1];
#pragma unroll
                for (int half = 0; half < 2; half++) {
                    int row = rowBase + wm + mt * 16 + g + half * 8;
                    float v0 = acc[mt][nt][half * 2 + 0] + b0;
                    float v1 = acc[mt][nt][half * 2 + 1] + b1;
                    if (EPI == 1) {
                        v0 += resid[(size_t)row * N + col];
                        v1 += resid[(size_t)row * N + col + 1];
                    }
                    if (EPI == 2) {
                        float u0 = v0, u1 = v1;
                        float t0 = 0.7978845608028654f * (u0 + 0.044715f * u0 * u0 * u0);
                        float t1 = 0.7978845608028654f * (u1 + 0.044715f * u1 * u1 * u1);
                        v0 = tf32r(0.5f * u0 * (1.f + tanhf(t0)));
                        v1 = tf32r(0.5f * u1 * (1.f + tanhf(t1)));
                    }
                    *(float2*)&C[(size_t)row * N + col] = make_float2(v0, v1);
                }
            }
        }
    }
}

// ---------------------------------------------------------------------------
// Windowed attention with tf32 MMA; RoPE fused into the loader.
// ---------------------------------------------------------------------------
#define QST 76
#define SST 68
#define ATTN_SMEM ((3 * 64 * QST + 64 * SST) * 4)

__global__ __launch_bounds__(128) void attn_kernel(const float* __restrict__ qkv,
                                                   const float* __restrict__ cosb,
                                                   const float* __restrict__ sinb,
                                                   float* __restrict__ out)
{
    extern __shared__ float sm[];
    float* sq = sm;
    float* sk = sq + 64 * QST;
    float* sv = sk + 64 * QST;
    float* ss = sv + 64 * QST;

    const int w   = blockIdx.x >> 4;
    const int h   = blockIdx.x & 15;
    const int tid = threadIdx.x;
    const float scale = 0.11785113019775793f;   // 72^-0.5

    for (int p = tid; p < 64 * 36; p += 128) {
        int r = p / 36, d = p % 36;
        int tok = w * 64 + r;
        size_t base = (size_t)tok * (3 * HID) + h * HD;
        float c = cosb[tok * HD + d];
        float s = sinb[tok * HD + d];

        float q0 = qkv[base + d], q1 = qkv[base + d + 36];
        sq[r * QST + d]      = tf32r((q0 * c - q1 * s) * scale);
        sq[r * QST + d + 36] = tf32r((q1 * c + q0 * s) * scale);

        float k0 = qkv[base + HID + d], k1 = qkv[base + HID + d + 36];
        sk[r * QST + d]      = tf32r(k0 * c - k1 * s);
        sk[r * QST + d + 36] = tf32r(k1 * c + k0 * s);

        sv[r * QST + d]      = tf32r(qkv[base + 2 * HID + d]);
        sv[r * QST + d + 36] = tf32r(qkv[base + 2 * HID + d + 36]);
    }
    __syncthreads();

    const int lane = tid & 31, warp = tid >> 5;
    const int g = lane >> 2, t = lane & 3;
    const int rw = warp * 16;

    // scores = Q @ K^T
    {
        float c1[8][4];
#pragma unroll
        for (int nt = 0; nt < 8; nt++)
#pragma unroll
            for (int c = 0; c < 4; c++) c1[nt][c] = 0.f;

#pragma unroll
        for (int ks = 0; ks < 9; ks++) {
            int k8 = ks * 8;
            uint32_t a0 = __float_as_uint(sq[(rw + g    ) * QST + k8 + t    ]);
            uint32_t a1 = __float_as_uint(sq[(rw + g + 8) * QST + k8 + t    ]);
            uint32_t a2 = __float_as_uint(sq[(rw + g    ) * QST + k8 + t + 4]);
            uint32_t a3 = __float_as_uint(sq[(rw + g + 8) * QST + k8 + t + 4]);
#pragma unroll
            for (int nt = 0; nt < 8; nt++) {
                uint32_t b0 = __float_as_uint(sk[(nt * 8 + g) * QST + k8 + t    ]);
                uint32_t b1 = __float_as_uint(sk[(nt * 8 + g) * QST + k8 + t + 4]);
                MMA_TF32(c1[nt], a0, a1, a2, a3, b0, b1);
            }
        }
#pragma unroll
        for (int nt = 0; nt < 8; nt++) {
            *(float2*)&ss[(rw + g    ) * SST + nt * 8 + 2 * t] =
                make_float2(c1[nt][0], c1[nt][1]);
            *(float2*)&ss[(rw + g + 8) * SST + nt * 8 + 2 * t] =
                make_float2(c1[nt][2], c1[nt][3]);
        }
    }
    __syncthreads();

    // softmax
    {
        int r = tid >> 1, hf = tid & 1;
        float* row = ss + r * SST + hf * 32;
        float mx = -1e30f;
#pragma unroll
        for (int j = 0; j < 32; j++) mx = fmaxf(mx, row[j]);
        mx = fmaxf(mx, __shfl_xor_sync(0xFFFFFFFFu, mx, 1));
        float e[32], sum = 0.f;
#pragma unroll
        for (int j = 0; j < 32; j++) { e[j] = __expf(row[j] - mx); sum += e[j]; }
        sum += __shfl_xor_sync(0xFFFFFFFFu, sum, 1);
        float inv = 1.f / sum;
#pragma unroll
        for (int j = 0; j < 32; j++) row[j] = tf32r(e[j] * inv);
    }
    __syncthreads();

    // out = P @ V
    {
        float c2[9][4];
#pragma unroll
        for (int nt = 0; nt < 9; nt++)
#pragma unroll
            for (int c = 0; c < 4; c++) c2[nt][c] = 0.f;

#pragma unroll
        for (int ks = 0; ks < 8; ks++) {
            int k8 = ks * 8;
            uint32_t a0 = __float_as_uint(ss[(rw + g    ) * SST + k8 + t    ]);
            uint32_t a1 = __float_as_uint(ss[(rw + g + 8) * SST + k8 + t    ]);
            uint32_t a2 = __float_as_uint(ss[(rw + g    ) * SST + k8 + t + 4]);
            uint32_t a3 = __float_as_uint(ss[(rw + g + 8) * SST + k8 + t + 4]);
#pragma unroll
            for (int nt = 0; nt < 9; nt++) {
                uint32_t b0 = __float_as_uint(sv[(k8 + t    ) * QST + nt * 8 + g]);
                uint32_t b1 = __float_as_uint(sv[(k8 + t + 4) * QST + nt * 8 + g]);
                MMA_TF32(c2[nt], a0, a1, a2, a3, b0, b1);
            }
        }

#pragma unroll
        for (int nt = 0; nt < 9; nt++) {
            size_t o0 = (size_t)(w * 64 + rw + g) * HID + h * HD + nt * 8 + 2 * t;
            size_t o1 = o0 + (size_t)8 * HID;
            *(float2*)&out[o0] = make_float2(tf32r(c2[nt][0]), tf32r(c2[nt][1]));
            *(float2*)&out[o1] = make_float2(tf32r(c2[nt][2]), tf32r(c2[nt][3]));
        }
    }
}

// ---------------------------------------------------------------------------
// Launch
// ---------------------------------------------------------------------------
extern "C" void kernel_launch(void* const* d_in, const int* in_sizes, int n_in,
                              void* d_out, int out_size)
{
    const float* x      = (const float*)d_in[0];
    const float* cosb   = (const float*)d_in[1];
    const float* sinb   = (const float*)d_in[2];
    const float* qkv_w  = (const float*)d_in[4];
    const float* qkv_b  = (const float*)d_in[5];
    const float* proj_w = (const float*)d_in[6];
    const float* proj_b = (const float*)d_in[7];
    const float* ln1_w  = (const float*)d_in[8];
    const float* ln1_b  = (const float*)d_in[9];
    const float* ln2_w  = (const float*)d_in[10];
    const float* ln2_b  = (const float*)d_in[11];
    const float* fc1_w  = (const float*)d_in[12];
    const float* fc1_b  = (const float*)d_in[13];
    const float* fc2_w  = (const float*)d_in[14];
    const float* fc2_b  = (const float*)d_in[15];
    float* out = (float*)d_out;

    float *ph, *pqkv, *pattn, *px1, *pm, *pwqkv, *pwproj, *pwfc1, *pwfc2;
    cudaGetSymbolAddress((void**)&ph,     g_h);
    cudaGetSymbolAddress((void**)&pqkv,   g_qkv);
    cudaGetSymbolAddress((void**)&pattn,  g_attn);
    cudaGetSymbolAddress((void**)&px1,    g_x1);
    cudaGetSymbolAddress((void**)&pm,     g_m);
    cudaGetSymbolAddress((void**)&pwqkv,  g_wqkv);
    cudaGetSymbolAddress((void**)&pwproj, g_wproj);
    cudaGetSymbolAddress((void**)&pwfc1,  g_wfc1);
    cudaGetSymbolAddress((void**)&pwfc2,  g_wfc2);

    cudaFuncSetAttribute(attn_kernel,
                         cudaFuncAttributeMaxDynamicSharedMemorySize, ATTN_SMEM);
    cudaFuncSetAttribute(gemm_tf32<0>,
                         cudaFuncAttributeMaxDynamicSharedMemorySize, GEMM_SMEM);
    cudaFuncSetAttribute(gemm_tf32<1>,
                         cudaFuncAttributeMaxDynamicSharedMemorySize, GEMM_SMEM);
    cudaFuncSetAttribute(gemm_tf32<2>,
                         cudaFuncAttributeMaxDynamicSharedMemorySize, GEMM_SMEM);

    // 0) round weights to tf32
    {
        int n;
        n = HID * 3 * HID / 4;
        round_w_kernel<<<(n + 255) / 256, 256>>>(qkv_w,  pwqkv,  n);
        n = HID * HID / 4;
        round_w_kernel<<<(n + 255) / 256, 256>>>(proj_w, pwproj, n);
        n = HID * INTER / 4;
        round_w_kernel<<<(n + 255) / 256, 256>>>(fc1_w,  pwfc1,  n);
        n = INTER * HID / 4;
        round_w_kernel<<<(n + 255) / 256, 256>>>(fc2_w,  pwfc2,  n);
    }

    // 1) LN1(x) -> h
    ln_kernel<<<SEQ / 8, 256>>>(x, ln1_w, ln1_b, ph);

    // 2) qkv = h @ qkv_w + qkv_b
    gemm_tf32<0><<<dim3(3 * HID / 128, SEQ / 128), 128, GEMM_SMEM>>>(
        ph, pwqkv, qkv_b, nullptr, pqkv, SEQ, 3 * HID, HID);

    // 3) windowed attention (RoPE fused)
    attn_kernel<<<NWIN * HEADS, 128, ATTN_SMEM>>>(pqkv, cosb, sinb, pattn);

    // 4) x1 = x + attn @ proj_w + proj_b
    gemm_tf32<1><<<dim3(HID / 128, SEQ / 128), 128, GEMM_SMEM>>>(
        pattn, pwproj, proj_b, x, px1, SEQ, HID, HID);

    // 5) LN2(x1) -> h
    ln_kernel<<<SEQ / 8, 256>>>(px1, ln2_w, ln2_b, ph);

    // 6) m = gelu(h @ fc1_w + fc1_b)
    gemm_tf32<2><<<dim3((INTER + 127) / 128, SEQ / 128), 128, GEMM_SMEM>>>(
        ph, pwfc1, fc1_b, nullptr, pm, SEQ, INTER, HID);

    // 7) out = x1 + m @ fc2_w + fc2_b
    gemm_tf32<1><<<dim3(HID / 128, SEQ / 128), 128, GEMM_SMEM>>>(
        pm, pwfc2, fc2_b, px1, out, SEQ, HID, INTER);
}

// round 17
// speedup vs baseline: 1.7536x; 1.4701x over previous
#include <cuda_runtime.h>
#include <cuda_fp16.h>
#include <math.h>
#include <stdint.h>

#define SEQ   16384
#define HID   1152
#define HEADS 16
#define HD    72
#define INTER 4304
#define NWIN  256

// ---------------------------------------------------------------------------
// Scratch (device globals; no runtime allocation allowed)
// ---------------------------------------------------------------------------
__device__ float  g_qkv [(size_t)SEQ * 3 * HID];   // qkv (fp32, attention input)
__device__ float  g_x1  [(size_t)SEQ * HID];       // post-attention residual
__device__ __half g_h   [(size_t)SEQ * HID];       // LN out (fp16, GEMM A)
__device__ __half g_attn[(size_t)SEQ * HID];       // attention out (fp16)
__device__ __half g_m   [(size_t)SEQ * INTER];     // gelu out (fp16)
// weights transposed to [N][K] fp16
__device__ __half g_wqkv[(size_t)3 * HID * HID];
__device__ __half g_wproj[(size_t)HID * HID];
__device__ __half g_wfc1[(size_t)INTER * HID];
__device__ __half g_wfc2[(size_t)HID * INTER];

__device__ __forceinline__ float tf32r(float f)
{
    uint32_t u;
    asm("cvt.rna.tf32.f32 %0, %1;" : "=r"(u) : "f"(f));
    return __uint_as_float(u);
}

// ---------------------------------------------------------------------------
// Weight prep: W[K][N] fp32 -> Wt[N][K] fp16 (32x32 smem transpose)
// ---------------------------------------------------------------------------
__global__ void wprep_kernel(const float* __restrict__ W,
                             __half* __restrict__ Wt, int K, int N)
{
    __shared__ float tile[32][33];
    int tx = threadIdx.x, ty = threadIdx.y;   // block (32, 8)
#pragma unroll
    for (int j = 0; j < 4; j++) {
        int k = blockIdx.y * 32 + ty + j * 8;
        int n = blockIdx.x * 32 + tx;
        tile[ty + j * 8][tx] = (k < K && n < N) ? W[(size_t)k * N + n] : 0.f;
    }
    __syncthreads();
#pragma unroll
    for (int j = 0; j < 4; j++) {
        int n = blockIdx.x * 32 + ty + j * 8;
        int k = blockIdx.y * 32 + tx;
        if (n < N && k < K)
            Wt[(size_t)n * K + k] = __float2half_rn(tile[tx][ty + j * 8]);
    }
}

// ---------------------------------------------------------------------------
// LayerNorm: one warp per row -> fp16
// ---------------------------------------------------------------------------
__global__ void ln_kernel(const float* __restrict__ in,
                          const float* __restrict__ w,
                          const float* __restrict__ b,
                          __half* __restrict__ out)
{
    int warp = (blockIdx.x * blockDim.x + threadIdx.x) >> 5;
    int lane = threadIdx.x & 31;
    if (warp >= SEQ) return;

    const float* row = in + (size_t)warp * HID;
    float v[36];
    float s = 0.f, s2 = 0.f;
#pragma unroll
    for (int i = 0; i < 36; i++) {
        v[i] = row[lane + 32 * i];
        s  += v[i];
        s2 += v[i] * v[i];
    }
#pragma unroll
    for (int o = 16; o > 0; o >>= 1) {
        s  += __shfl_xor_sync(0xFFFFFFFFu, s,  o);
        s2 += __shfl_xor_sync(0xFFFFFFFFu, s2, o);
    }
    float mean = s * (1.0f / HID);
    float var  = s2 * (1.0f / HID) - mean * mean;
    float rstd = rsqrtf(var + 1e-6f);

    __half* orow = out + (size_t)warp * HID;
#pragma unroll
    for (int i = 0; i < 36; i++) {
        int c = lane + 32 * i;
        orow[c] = __float2half_rn((v[i] - mean) * rstd * w[c] + b[c]);
    }
}

// ---------------------------------------------------------------------------
// fp16 tensor-core GEMM: C[M,N] = A[M,K] @ B^T  (B stored [N][K] fp16)
// 128x128x32 CTA tile, 128 threads = 4 warps (2x2), 64x64 per warp,
// ldmatrix fragment loads, 4-stage cp.async pipeline.
// EPI: 0 = bias -> fp32, 1 = bias + resid -> fp32, 2 = bias + gelu -> fp16
// ---------------------------------------------------------------------------
#define BK 32
#define ASTW 20                         // words per row: 16 data + 4 pad
#define TILE_W (128 * ASTW)             // 2560 words per tile
#define STAGE_W (2 * TILE_W)            // A + B
#define NSTAGE 4
#define GSMEM (NSTAGE * STAGE_W * 4)    // 81920 bytes

#define MMA_F16(acc, a0, a1, a2, a3, b0, b1)                                   \
    asm volatile(                                                              \
        "mma.sync.aligned.m16n8k16.row.col.f32.f16.f16.f32 "                   \
        "{%0,%1,%2,%3}, {%4,%5,%6,%7}, {%8,%9}, {%0,%1,%2,%3};\n"              \
        : "+f"(acc[0]), "+f"(acc[1]), "+f"(acc[2]), "+f"(acc[3])               \
        : "r"(a0), "r"(a1), "r"(a2), "r"(a3), "r"(b0), "r"(b1))

#define LDSM_X4(r0, r1, r2, r3, addr)                                          \
    asm volatile("ldmatrix.sync.aligned.m8n8.x4.shared.b16 {%0,%1,%2,%3}, [%4];" \
                 : "=r"(r0), "=r"(r1), "=r"(r2), "=r"(r3) : "r"(addr))

template <int EPI>
__global__ __launch_bounds__(128) void gemm_f16(
    const __half* __restrict__ A, const __half* __restrict__ B,
    const float* __restrict__ bias, const float* __restrict__ resid,
    float* __restrict__ Cf, __half* __restrict__ Ch, int M, int N, int K)
{
    extern __shared__ float smf[];
    const uint32_t smemBase = (uint32_t)__cvta_generic_to_shared(smf);

    const int tid  = threadIdx.x;
    const int lane = tid & 31, warp = tid >> 5;
    const int g = lane >> 2, t = lane & 3;
    const int wm = (warp >> 1) * 64, wn = (warp & 1) * 64;
    const int rowBase = blockIdx.y * 128, colBase = blockIdx.x * 128;

    float acc[4][8][4];
#pragma unroll
    for (int i = 0; i < 4; i++)
#pragma unroll
        for (int j = 0; j < 8; j++)
#pragma unroll
            for (int c = 0; c < 4; c++) acc[i][j][c] = 0.f;

    const int nkt = (K + BK - 1) / BK;

    // cp.async loaders: 4 chunks of 16B per thread per tile
    auto loadChunk = [&](int ck) {
        int stage = ck & (NSTAGE - 1);
        int k0 = ck * BK;
        uint32_t sA = smemBase + stage * STAGE_W * 4;
        uint32_t sB = sA + TILE_W * 4;
#pragma unroll
        for (int i = 0; i < 4; i++) {
            int c  = tid + i * 128;
            int m  = c >> 2, ch = c & 3;
            int gk = k0 + ch * 8;
            int sz = (gk < K) ? 16 : 0;
            const __half* src = A + (size_t)(rowBase + m) * K + min(gk, K - 8);
            uint32_t dst = sA + (m * ASTW + ch * 4) * 4;
            asm volatile("cp.async.cg.shared.global [%0], [%1], 16, %2;\n"
                         :: "r"(dst), "l"(src), "r"(sz));
        }
#pragma unroll
        for (int i = 0; i < 4; i++) {
            int c  = tid + i * 128;
            int n  = c >> 2, ch = c & 3;
            int gn = colBase + n;
            int gk = k0 + ch * 8;
            int sz = (gn < N && gk < K) ? 16 : 0;
            const __half* src = B + (size_t)min(gn, N - 1) * K + min(gk, K - 8);
            uint32_t dst = sB + (n * ASTW + ch * 4) * 4;
            asm volatile("cp.async.cg.shared.global [%0], [%1], 16, %2;\n"
                         :: "r"(dst), "l"(src), "r"(sz));
        }
    };

    // ldmatrix lane-address components (word units)
    const int aRow  = wm + (lane & 15);
    const int aOffW = (lane >> 4) * 4;                     // k-half select
    const int bRow  = wn + ((lane >> 4) << 3) + (lane & 7); // n row (+8 for hi pair)
    const int bOffW = ((lane >> 3) & 1) * 4;               // k-half select

    // prologue: chunks 0..NSTAGE-2
#pragma unroll
    for (int p = 0; p < NSTAGE - 1; p++) {
        if (p < nkt) loadChunk(p);
        asm volatile("cp.async.commit_group;\n");
    }

    for (int kt = 0; kt < nkt; kt++) {
        asm volatile("cp.async.wait_group %0;\n" :: "n"(NSTAGE - 2));
        __syncthreads();

        if (kt + NSTAGE - 1 < nkt) loadChunk(kt + NSTAGE - 1);
        asm volatile("cp.async.commit_group;\n");

        int stage = kt & (NSTAGE - 1);
        uint32_t sA = smemBase + stage * STAGE_W * 4;
        uint32_t sB = sA + TILE_W * 4;

#pragma unroll
        for (int ks = 0; ks < 2; ks++) {           // two k16 steps per chunk
            const int kw = ks * 8;                 // word offset for this k16
            uint32_t af[4][4], bf[8][2];
#pragma unroll
            for (int mt = 0; mt < 4; mt++) {
                uint32_t addr = sA + ((aRow + mt * 16) * ASTW + aOffW + kw) * 4;
                LDSM_X4(af[mt][0], af[mt][1], af[mt][2], af[mt][3], addr);
            }
#pragma unroll
            for (int p = 0; p < 4; p++) {          // n-tile pairs
                uint32_t addr = sB + ((bRow + p * 16) * ASTW + bOffW + kw) * 4;
                // non-trans: B stored [N][K]; thread t needs consecutive k at
                // fixed n=t/4, which is exactly the native ldmatrix fragment.
                LDSM_X4(bf[2 * p][0], bf[2 * p][1],
                        bf[2 * p + 1][0], bf[2 * p + 1][1], addr);
            }
#pragma unroll
            for (int mt = 0; mt < 4; mt++)
#pragma unroll
                for (int nt = 0; nt < 8; nt++)
                    MMA_F16(acc[mt][nt], af[mt][0], af[mt][1], af[mt][2],
                            af[mt][3], bf[nt][0], bf[nt][1]);
        }
        __syncthreads();
    }

    // epilogue
#pragma unroll
    for (int mt = 0; mt < 4; mt++) {
#pragma unroll
        for (int nt = 0; nt < 8; nt++) {
            int col = colBase + wn + nt * 8 + 2 * t;
            if (col < N) {
                float b0 = bias[col], b1 = bias[col + 1];
#pragma unroll
                for (int half = 0; half < 2; half++) {
                    int row = rowBase + wm + mt * 16 + g + half * 8;
                    float v0 = acc[mt][nt][half * 2 + 0] + b0;
                    float v1 = acc[mt][nt][half * 2 + 1] + b1;
                    if (EPI == 1) {
                        v0 += resid[(size_t)row * N + col];
                        v1 += resid[(size_t)row * N + col + 1];
                    }
                    if (EPI == 2) {
                        float u0 = v0, u1 = v1;
                        float t0 = 0.7978845608028654f * (u0 + 0.044715f * u0 * u0 * u0);
                        float t1 = 0.7978845608028654f * (u1 + 0.044715f * u1 * u1 * u1);
                        v0 = 0.5f * u0 * (1.f + tanhf(t0));
                        v1 = 0.5f * u1 * (1.f + tanhf(t1));
                        *(__half2*)&Ch[(size_t)row * N + col] =
                            __floats2half2_rn(v0, v1);
                    } else {
                        *(float2*)&Cf[(size_t)row * N + col] = make_float2(v0, v1);
                    }
                }
            }
        }
    }
}

// ---------------------------------------------------------------------------
// Windowed attention with tf32 MMA; RoPE fused; outputs fp16.
// ---------------------------------------------------------------------------
#define QST 76
#define SST 68
#define ATTN_SMEM ((3 * 64 * QST + 64 * SST) * 4)

#define MMA_TF32(acc, a0, a1, a2, a3, b0, b1)                                  \
    asm volatile(                                                              \
        "mma.sync.aligned.m16n8k8.row.col.f32.tf32.tf32.f32 "                  \
        "{%0,%1,%2,%3}, {%4,%5,%6,%7}, {%8,%9}, {%0,%1,%2,%3};\n"              \
        : "+f"(acc[0]), "+f"(acc[1]), "+f"(acc[2]), "+f"(acc[3])               \
        : "r"(a0), "r"(a1), "r"(a2), "r"(a3), "r"(b0), "r"(b1))

__global__ __launch_bounds__(128) void attn_kernel(const float* __restrict__ qkv,
                                                   const float* __restrict__ cosb,
                                                   const float* __restrict__ sinb,
                                                   __half* __restrict__ out)
{
    extern __shared__ float sm[];
    float* sq = sm;
    float* sk = sq + 64 * QST;
    float* sv = sk + 64 * QST;
    float* ss = sv + 64 * QST;

    const int w   = blockIdx.x >> 4;
    const int h   = blockIdx.x & 15;
    const int tid = threadIdx.x;
    const float scale = 0.11785113019775793f;   // 72^-0.5

    for (int p = tid; p < 64 * 36; p += 128) {
        int r = p / 36, d = p % 36;
        int tok = w * 64 + r;
        size_t base = (size_t)tok * (3 * HID) + h * HD;
        float c = cosb[tok * HD + d];
        float s = sinb[tok * HD + d];

        float q0 = qkv[base + d], q1 = qkv[base + d + 36];
        sq[r * QST + d]      = tf32r((q0 * c - q1 * s) * scale);
        sq[r * QST + d + 36] = tf32r((q1 * c + q0 * s) * scale);

        float k0 = qkv[base + HID + d], k1 = qkv[base + HID + d + 36];
        sk[r * QST + d]      = tf32r(k0 * c - k1 * s);
        sk[r * QST + d + 36] = tf32r(k1 * c + k0 * s);

        sv[r * QST + d]      = tf32r(qkv[base + 2 * HID + d]);
        sv[r * QST + d + 36] = tf32r(qkv[base + 2 * HID + d + 36]);
    }
    __syncthreads();

    const int lane = tid & 31, warp = tid >> 5;
    const int g = lane >> 2, t = lane & 3;
    const int rw = warp * 16;

    // scores = Q @ K^T
    {
        float c1[8][4];
#pragma unroll
        for (int nt = 0; nt < 8; nt++)
#pragma unroll
            for (int c = 0; c < 4; c++) c1[nt][c] = 0.f;

#pragma unroll
        for (int ks = 0; ks < 9; ks++) {
            int k8 = ks * 8;
            uint32_t a0 = __float_as_uint(sq[(rw + g    ) * QST + k8 + t    ]);
            uint32_t a1 = __float_as_uint(sq[(rw + g + 8) * QST + k8 + t    ]);
            uint32_t a2 = __float_as_uint(sq[(rw + g    ) * QST + k8 + t + 4]);
            uint32_t a3 = __float_as_uint(sq[(rw + g + 8) * QST + k8 + t + 4]);
#pragma unroll
            for (int nt = 0; nt < 8; nt++) {
                uint32_t b0 = __float_as_uint(sk[(nt * 8 + g) * QST + k8 + t    ]);
                uint32_t b1 = __float_as_uint(sk[(nt * 8 + g) * QST + k8 + t + 4]);
                MMA_TF32(c1[nt], a0, a1, a2, a3, b0, b1);
            }
        }
#pragma unroll
        for (int nt = 0; nt < 8; nt++) {
            *(float2*)&ss[(rw + g    ) * SST + nt * 8 + 2 * t] =
                make_float2(c1[nt][0], c1[nt][1]);
            *(float2*)&ss[(rw + g + 8) * SST + nt * 8 + 2 * t] =
                make_float2(c1[nt][2], c1[nt][3]);
        }
    }
    __syncthreads();

    // softmax
    {
        int r = tid >> 1, hf = tid & 1;
        float* row = ss + r * SST + hf * 32;
        float mx = -1e30f;
#pragma unroll
        for (int j = 0; j < 32; j++) mx = fmaxf(mx, row[j]);
        mx = fmaxf(mx, __shfl_xor_sync(0xFFFFFFFFu, mx, 1));
        float e[32], sum = 0.f;
#pragma unroll
        for (int j = 0; j < 32; j++) { e[j] = __expf(row[j] - mx); sum += e[j]; }
        sum += __shfl_xor_sync(0xFFFFFFFFu, sum, 1);
        float inv = 1.f / sum;
#pragma unroll
        for (int j = 0; j < 32; j++) row[j] = tf32r(e[j] * inv);
    }
    __syncthreads();

    // out = P @ V -> fp16
    {
        float c2[9][4];
#pragma unroll
        for (int nt = 0; nt < 9; nt++)
#pragma unroll
            for (int c = 0; c < 4; c++) c2[nt][c] = 0.f;

#pragma unroll
        for (int ks = 0; ks < 8; ks++) {
            int k8 = ks * 8;
            uint32_t a0 = __float_as_uint(ss[(rw + g    ) * SST + k8 + t    ]);
            uint32_t a1 = __float_as_uint(ss[(rw + g + 8) * SST + k8 + t    ]);
            uint32_t a2 = __float_as_uint(ss[(rw + g    ) * SST + k8 + t + 4]);
            uint32_t a3 = __float_as_uint(ss[(rw + g + 8) * SST + k8 + t + 4]);
#pragma unroll
            for (int nt = 0; nt < 9; nt++) {
                uint32_t b0 = __float_as_uint(sv[(k8 + t    ) * QST + nt * 8 + g]);
                uint32_t b1 = __float_as_uint(sv[(k8 + t + 4) * QST + nt * 8 + g]);
                MMA_TF32(c2[nt], a0, a1, a2, a3, b0, b1);
            }
        }

#pragma unroll
        for (int nt = 0; nt < 9; nt++) {
            size_t o0 = (size_t)(w * 64 + rw + g) * HID + h * HD + nt * 8 + 2 * t;
            size_t o1 = o0 + (size_t)8 * HID;
            *(__half2*)&out[o0] = __floats2half2_rn(c2[nt][0], c2[nt][1]);
            *(__half2*)&out[o1] = __floats2half2_rn(c2[nt][2], c2[nt][3]);
        }
    }
}

// ---------------------------------------------------------------------------
// Launch
// ---------------------------------------------------------------------------
extern "C" void kernel_launch(void* const* d_in, const int* in_sizes, int n_in,
                              void* d_out, int out_size)
{
    const float* x      = (const float*)d_in[0];
    const float* cosb   = (const float*)d_in[1];
    const float* sinb   = (const float*)d_in[2];
    const float* qkv_w  = (const float*)d_in[4];
    const float* qkv_b  = (const float*)d_in[5];
    const float* proj_w = (const float*)d_in[6];
    const float* proj_b = (const float*)d_in[7];
    const float* ln1_w  = (const float*)d_in[8];
    const float* ln1_b  = (const float*)d_in[9];
    const float* ln2_w  = (const float*)d_in[10];
    const float* ln2_b  = (const float*)d_in[11];
    const float* fc1_w  = (const float*)d_in[12];
    const float* fc1_b  = (const float*)d_in[13];
    const float* fc2_w  = (const float*)d_in[14];
    const float* fc2_b  = (const float*)d_in[15];
    float* out = (float*)d_out;

    float *pqkv, *px1;
    __half *ph, *pattn, *pm, *pwqkv, *pwproj, *pwfc1, *pwfc2;
    cudaGetSymbolAddress((void**)&pqkv,   g_qkv);
    cudaGetSymbolAddress((void**)&px1,    g_x1);
    cudaGetSymbolAddress((void**)&ph,     g_h);
    cudaGetSymbolAddress((void**)&pattn,  g_attn);
    cudaGetSymbolAddress((void**)&pm,     g_m);
    cudaGetSymbolAddress((void**)&pwqkv,  g_wqkv);
    cudaGetSymbolAddress((void**)&pwproj, g_wproj);
    cudaGetSymbolAddress((void**)&pwfc1,  g_wfc1);
    cudaGetSymbolAddress((void**)&pwfc2,  g_wfc2);

    cudaFuncSetAttribute(attn_kernel,
                         cudaFuncAttributeMaxDynamicSharedMemorySize, ATTN_SMEM);
    cudaFuncSetAttribute(gemm_f16<0>,
                         cudaFuncAttributeMaxDynamicSharedMemorySize, GSMEM);
    cudaFuncSetAttribute(gemm_f16<1>,
                         cudaFuncAttributeMaxDynamicSharedMemorySize, GSMEM);
    cudaFuncSetAttribute(gemm_f16<2>,
                         cudaFuncAttributeMaxDynamicSharedMemorySize, GSMEM);

    // 0) transpose + convert weights to fp16 [N][K]
    {
        dim3 blk(32, 8);
        wprep_kernel<<<dim3((3 * HID + 31) / 32, (HID + 31) / 32), blk>>>(
            qkv_w, pwqkv, HID, 3 * HID);
        wprep_kernel<<<dim3((HID + 31) / 32, (HID + 31) / 32), blk>>>(
            proj_w, pwproj, HID, HID);
        wprep_kernel<<<dim3((INTER + 31) / 32, (HID + 31) / 32), blk>>>(
            fc1_w, pwfc1, HID, INTER);
        wprep_kernel<<<dim3((HID + 31) / 32, (INTER + 31) / 32), blk>>>(
            fc2_w, pwfc2, INTER, HID);
    }

    // 1) LN1(x) -> h (fp16)
    ln_kernel<<<SEQ / 8, 256>>>(x, ln1_w, ln1_b, ph);

    // 2) qkv = h @ qkv_w + qkv_b  (fp32 out)
    gemm_f16<0><<<dim3((3 * HID + 127) / 128, SEQ / 128), 128, GSMEM>>>(
        ph, pwqkv, qkv_b, nullptr, pqkv, nullptr, SEQ, 3 * HID, HID);

    // 3) windowed attention (RoPE fused) -> fp16
    attn_kernel<<<NWIN * HEADS, 128, ATTN_SMEM>>>(pqkv, cosb, sinb, pattn);

    // 4) x1 = x + attn @ proj_w + proj_b  (fp32)
    gemm_f16<1><<<dim3((HID + 127) / 128, SEQ / 128), 128, GSMEM>>>(
        pattn, pwproj, proj_b, x, px1, nullptr, SEQ, HID, HID);

    // 5) LN2(x1) -> h (fp16)
    ln_kernel<<<SEQ / 8, 256>>>(px1, ln2_w, ln2_b, ph);

    // 6) m = gelu(h @ fc1_w + fc1_b)  (fp16 out)
    gemm_f16<2><<<dim3((INTER + 127) / 128, SEQ / 128), 128, GSMEM>>>(
        ph, pwfc1, fc1_b, nullptr, nullptr, pm, SEQ, INTER, HID);

    // 7) out = x1 + m @ fc2_w + fc2_b  (fp32)
    gemm_f16<1><<<dim3((HID + 127) / 128, SEQ / 128), 128, GSMEM>>>(
        pm, pwfc2, fc2_b, px1, out, nullptr, SEQ, HID, INTER);
}